// round 9
// baseline (speedup 1.0000x reference)
#include <cuda_runtime.h>
#include <cstdint>

// ---------------------------------------------------------------------------
// 2-layer GAT, softmax-free, dst-bucketed CSR, persistent work-stealing warps.
// Outputs (tuple order): out2 [N,8] then x_emb [N,64]
// ---------------------------------------------------------------------------

#define NODES 100000
#define EDGES 1600000
#define EPMAX (NODES + EDGES)
#define CAP   96
#define FULLM 0xffffffffu
#define CHUNK 4

__device__ float g_xl1[(size_t)NODES * 64];
__device__ float g_as1[NODES * 4];
__device__ float g_ad1[NODES * 4];
__device__ float g_xl2[NODES * 8];
__device__ float g_as2[NODES];
__device__ float g_ad2[NODES];
__device__ int   g_cnt[NODES];
__device__ int   g_csr[(size_t)NODES * CAP];
__device__ int   g_is64;
__device__ int   g_ticket1;
__device__ int   g_ticket2;

__device__ __forceinline__ float lrelu(float x) {
    return x > 0.0f ? x : 0.2f * x;
}

__device__ __forceinline__ void edge_sd(const int* __restrict__ ei, int i, int E,
                                        int is64, int& s, int& d) {
    if (i < E) {
        if (is64) { s = ei[2 * i]; d = ei[2 * (E + i)]; }
        else      { s = ei[i];     d = ei[E + i]; }
    } else {
        s = d = i - E;
    }
}

// Detect edge dtype width (int64 vs int32): int64 LE with ids < 2^31 has every
// odd 32-bit word zero.
__global__ void detect_kernel(const int* __restrict__ ei32, int nwords) {
    __shared__ int any;
    if (threadIdx.x == 0) any = 0;
    __syncthreads();
    for (int i = threadIdx.x * 2 + 1; i < nwords; i += 2 * blockDim.x) {
        if (ei32[i] != 0) { any = 1; break; }
    }
    __syncthreads();
    if (threadIdx.x == 0) g_is64 = any ? 0 : 1;
}

// Padded-CSR build: bucket src ids by dst.
__global__ void csr_build(const int* __restrict__ ei, int E, int EP) {
    int i = blockIdx.x * 256 + threadIdx.x;
    if (i >= EP) return;
    int s, d; edge_sd(ei, i, E, g_is64, s, d);
    int pos = atomicAdd(&g_cnt[d], 1);
    if (pos < CAP) g_csr[(size_t)d * CAP + pos] = s;
}

// ---------------------------------------------------------------------------
// GEMM1: xl1 = x @ W1 ([N,128]@[128,64]) + per-(node,head) alpha_s/alpha_d.
// ---------------------------------------------------------------------------
#define GEMM1_SMEM ((128*64 + 128*68 + 512 + 512) * 4)

__global__ void gemm1_kernel(const float* __restrict__ x, const float* __restrict__ W1,
                             const float* __restrict__ asw, const float* __restrict__ adw,
                             int N) {
    extern __shared__ float smem[];
    float* sW  = smem;
    float* sX  = sW + 128 * 64;
    float* sAS = sX + 128 * 68;
    float* sAD = sAS + 512;

    int t = threadIdx.x;
    int nb = blockIdx.x * 128;

    const float4* W4 = (const float4*)W1;
    float4* sW4 = (float4*)sW;
    for (int i = t; i < 2048; i += 256) sW4[i] = W4[i];
    sAS[t] = 0.0f; sAS[t + 256] = 0.0f;
    sAD[t] = 0.0f; sAD[t + 256] = 0.0f;

    int tx = t & 15, ty = t >> 4;
    int c0 = tx * 4, n0 = ty * 8;
    float acc[8][4] = {};

    for (int kb = 0; kb < 2; kb++) {
        __syncthreads();
        for (int i = t; i < 2048; i += 256) {
            int r = i >> 4, j = i & 15;
            float4 v = make_float4(0.f, 0.f, 0.f, 0.f);
            if (nb + r < N)
                v = ((const float4*)x)[(size_t)(nb + r) * 32 + kb * 16 + j];
            *(float4*)(&sX[r * 68 + j * 4]) = v;
        }
        __syncthreads();
#pragma unroll 4
        for (int k = 0; k < 64; k++) {
            float4 w = *(const float4*)(&sW[(kb * 64 + k) * 64 + c0]);
#pragma unroll
            for (int i = 0; i < 8; i++) {
                float xv = sX[(n0 + i) * 68 + k];
                acc[i][0] = fmaf(xv, w.x, acc[i][0]);
                acc[i][1] = fmaf(xv, w.y, acc[i][1]);
                acc[i][2] = fmaf(xv, w.z, acc[i][2]);
                acc[i][3] = fmaf(xv, w.w, acc[i][3]);
            }
        }
    }

    int h = tx >> 2;
    float4 aw = *(const float4*)(asw + c0);
    float4 dw = *(const float4*)(adw + c0);
#pragma unroll
    for (int i = 0; i < 8; i++) {
        int node = nb + n0 + i;
        if (node < N) {
            float4 v = make_float4(acc[i][0], acc[i][1], acc[i][2], acc[i][3]);
            *(float4*)(&g_xl1[(size_t)node * 64 + c0]) = v;
            float ps = v.x * aw.x + v.y * aw.y + v.z * aw.z + v.w * aw.w;
            float pd = v.x * dw.x + v.y * dw.y + v.z * dw.z + v.w * dw.w;
            atomicAdd(&sAS[(n0 + i) * 4 + h], ps);
            atomicAdd(&sAD[(n0 + i) * 4 + h], pd);
        }
    }
    __syncthreads();
#pragma unroll
    for (int rep = 0; rep < 2; rep++) {
        int idx = rep * 256 + t;
        int node = nb + (idx >> 2);
        if (node < N) {
            g_as1[node * 4 + (idx & 3)] = sAS[idx];
            g_ad1[node * 4 + (idx & 3)] = sAD[idx];
        }
    }
}

// ---------------------------------------------------------------------------
// Layer-1 aggregation + layer-2 prep. Persistent warps steal CHUNK-node
// batches via g_ticket1. Per node: 8-edge batches, pipelined src-id AND
// as1-value prefetch; gather = half-warp x float4, 2 edges in flight.
// ---------------------------------------------------------------------------
__global__ void edge1_agg(const float* __restrict__ b1, const float* __restrict__ W2,
                          const float* __restrict__ as2w, const float* __restrict__ ad2w,
                          float* __restrict__ xemb, int N) {
    __shared__ float sW2t[512];  // sW2t[j*64 + c] = W2[c*8 + j]
    __shared__ float sB1[64];
    __shared__ float sA2[8], sD2[8];
    int t = threadIdx.x;
    for (int i = t; i < 512; i += 256) {
        int c = i & 63, j = i >> 6;
        sW2t[j * 64 + c] = W2[c * 8 + j];
    }
    if (t < 64) sB1[t] = b1[t];
    if (t < 8)  { sA2[t] = as2w[t]; sD2[t] = ad2w[t]; }
    __syncthreads();

    int lane = t & 31;
    int hw = lane >> 4, l16 = lane & 15;
    int hg = l16 >> 2;
    int he = lane & 3;        // ev-phase head
    int qe = lane >> 2;       // ev-phase edge slot (0..7)

    for (;;) {
        int n0;
        if (lane == 0) n0 = atomicAdd(&g_ticket1, CHUNK);
        n0 = __shfl_sync(FULLM, n0, 0);
        if (n0 >= N) return;
        int n1 = n0 + CHUNK; if (n1 > N) n1 = N;

        for (int d = n0; d < n1; d++) {
            int k = g_cnt[d]; if (k > CAP) k = CAP;
            const int* __restrict__ row = &g_csr[(size_t)d * CAP];
            float adv_e = g_ad1[d * 4 + he];

            float4 acc = make_float4(0.f, 0.f, 0.f, 0.f);
            float evsum = 0.0f;

            // prologue: batch-0 ids + as1 values
            int sv = ((lane & 7) < k) ? row[lane & 7] : 0;
            int se = __shfl_sync(FULLM, sv, qe);
            float av = (qe < k) ? g_as1[se * 4 + he] : 0.0f;
            bool valid = (qe < k);

            for (int base = 0; base < k; base += 8) {
                // prefetch next batch ids + as1 values
                int jn = base + 8 + (lane & 7);
                int svn = (jn < k) ? row[jn] : 0;
                int sen = __shfl_sync(FULLM, svn, qe);
                bool validn = (base + 8 + qe < k);
                float avn = validn ? g_as1[sen * 4 + he] : 0.0f;

                float ev = valid ? __expf(lrelu(av + adv_e)) : 0.0f;
                evsum += ev;

                int m = k - base; if (m > 8) m = 8;
#pragma unroll
                for (int jj = 0; jj < 4; jj++) {
                    int j = 2 * jj + hw;
                    int sj = __shfl_sync(FULLM, sv, j);
                    float evh = __shfl_sync(FULLM, ev, j * 4 + hg);
                    if (j < m) {
                        float4 xv = *(const float4*)&g_xl1[(size_t)sj * 64 + l16 * 4];
                        acc.x = fmaf(evh, xv.x, acc.x);
                        acc.y = fmaf(evh, xv.y, acc.y);
                        acc.z = fmaf(evh, xv.z, acc.z);
                        acc.w = fmaf(evh, xv.w, acc.w);
                    }
                }
                sv = svn; av = avn; valid = validn;
            }

            acc.x += __shfl_xor_sync(FULLM, acc.x, 16);
            acc.y += __shfl_xor_sync(FULLM, acc.y, 16);
            acc.z += __shfl_xor_sync(FULLM, acc.z, 16);
            acc.w += __shfl_xor_sync(FULLM, acc.w, 16);

            evsum += __shfl_xor_sync(FULLM, evsum, 16);
            evsum += __shfl_xor_sync(FULLM, evsum, 8);
            evsum += __shfl_xor_sync(FULLM, evsum, 4);
            float inv = 1.0f / (evsum + 1e-16f);
            float invh = __shfl_sync(FULLM, inv, hg);

            float4 bb = *(const float4*)&sB1[l16 * 4];
            float4 v;
            v.x = acc.x * invh + bb.x;
            v.y = acc.y * invh + bb.y;
            v.z = acc.z * invh + bb.z;
            v.w = acc.w * invh + bb.w;
            if (hw == 0)
                *(float4*)&xemb[(size_t)d * 64 + l16 * 4] = v;

            float4 hv = make_float4(fmaxf(v.x, 0.f), fmaxf(v.y, 0.f),
                                    fmaxf(v.z, 0.f), fmaxf(v.w, 0.f));
            float p[8];
#pragma unroll
            for (int j = 0; j < 8; j++) {
                float4 w = *(const float4*)&sW2t[j * 64 + l16 * 4];
                p[j] = hv.x * w.x + hv.y * w.y + hv.z * w.z + hv.w * w.w;
            }
#pragma unroll
            for (int off = 8; off; off >>= 1)
#pragma unroll
                for (int j = 0; j < 8; j++)
                    p[j] += __shfl_xor_sync(FULLM, p[j], off);

            if (lane == 0) {
                float ss = 0.f, dd = 0.f;
#pragma unroll
                for (int j = 0; j < 8; j++) {
                    ss = fmaf(p[j], sA2[j], ss);
                    dd = fmaf(p[j], sD2[j], dd);
                }
                *(float4*)&g_xl2[d * 8]     = make_float4(p[0], p[1], p[2], p[3]);
                *(float4*)&g_xl2[d * 8 + 4] = make_float4(p[4], p[5], p[6], p[7]);
                g_as2[d] = ss;
                g_ad2[d] = dd;
            }
        }
    }
}

// ---------------------------------------------------------------------------
// Layer-2 aggregation + finalize, persistent work-stealing warps.
// ---------------------------------------------------------------------------
__global__ void edge2_agg(const float* __restrict__ b2, float* __restrict__ out2,
                          int N) {
    int t = threadIdx.x, lane = t & 31;
    int g = lane >> 3, c = lane & 7;

    for (;;) {
        int n0;
        if (lane == 0) n0 = atomicAdd(&g_ticket2, CHUNK);
        n0 = __shfl_sync(FULLM, n0, 0);
        if (n0 >= N) return;
        int n1 = n0 + CHUNK; if (n1 > N) n1 = N;

        for (int d = n0; d < n1; d++) {
            int k = g_cnt[d]; if (k > CAP) k = CAP;
            const int* __restrict__ row = &g_csr[(size_t)d * CAP];
            float adv = g_ad2[d];

            float acc = 0.0f, evsum = 0.0f;
            for (int base = 0; base < k; base += 32) {
                int jl = base + lane;
                int sv = 0; float ev = 0.0f;
                if (jl < k) {
                    sv = row[jl];
                    ev = __expf(lrelu(g_as2[sv] + adv));
                }
                evsum += ev;
                int m = k - base; if (m > 32) m = 32;
                for (int jj = 0; jj * 4 < m; jj++) {
                    int j = jj * 4 + g;
                    int sj = __shfl_sync(FULLM, sv, j);
                    float evh = __shfl_sync(FULLM, ev, j);
                    if (j < m) acc = fmaf(evh, g_xl2[sj * 8 + c], acc);
                }
            }
#pragma unroll
            for (int off = 16; off; off >>= 1)
                evsum += __shfl_xor_sync(FULLM, evsum, off);
            acc += __shfl_down_sync(FULLM, acc, 16);
            acc += __shfl_down_sync(FULLM, acc, 8);
            if (lane < 8)
                out2[(size_t)d * 8 + c] = acc / (evsum + 1e-16f) + b2[c];
        }
    }
}

__global__ void reset_tickets() {
    g_ticket1 = 0;
    g_ticket2 = 0;
}

// ---------------------------------------------------------------------------
extern "C" void kernel_launch(void* const* d_in, const int* in_sizes, int n_in,
                              void* d_out, int out_size) {
    const float* x    = (const float*)d_in[0];
    const int*   ei   = (const int*)d_in[1];
    const float* W1   = (const float*)d_in[2];
    const float* as1w = (const float*)d_in[3];
    const float* ad1w = (const float*)d_in[4];
    const float* b1   = (const float*)d_in[5];
    const float* W2   = (const float*)d_in[6];
    const float* as2w = (const float*)d_in[7];
    const float* ad2w = (const float*)d_in[8];
    const float* b2   = (const float*)d_in[9];
    float* out = (float*)d_out;

    int N  = in_sizes[0] / 128;
    int E  = in_sizes[1] / 2;
    int EP = E + N;

    float* out2 = out;                    // [N, 8]
    float* xemb = out + (size_t)N * 8;    // [N, 64]

    void* cntp = nullptr;
    cudaGetSymbolAddress(&cntp, g_cnt);
    cudaFuncSetAttribute(gemm1_kernel, cudaFuncAttributeMaxDynamicSharedMemorySize,
                         GEMM1_SMEM);

    cudaMemsetAsync(cntp, 0, (size_t)N * sizeof(int));
    reset_tickets<<<1, 1>>>();

    {
        int nwords = in_sizes[1];
        if (nwords > 16384) nwords = 16384;
        detect_kernel<<<1, 256>>>(ei, nwords);
    }

    csr_build<<<(EP + 255) / 256, 256>>>(ei, E, EP);

    gemm1_kernel<<<(N + 127) / 128, 256, GEMM1_SMEM>>>(x, W1, as1w, ad1w, N);

    // persistent kernels: enough blocks to fill the chip; extras exit fast
    edge1_agg<<<1024, 256>>>(b1, W2, as2w, ad2w, xemb, N);

    edge2_agg<<<1024, 256>>>(b2, out2, N);
}